// round 5
// baseline (speedup 1.0000x reference)
#include <cuda_runtime.h>
#include <cuda_bf16.h>
#include <cstdint>

#define NROWS  8192
#define HALF_N 4096
#define D      256
#define MT     128            // rows per CTA
#define NT     256            // cols per j-tile
#define NSTEP  32             // pipeline steps = (4096/NT) * 2 K-halves
#define THREADS 256

// smem: A tile @0 (64KB, full K), B buf0 @65536 (64KB, K-half), B buf1 @131072
#define SM_A  0
#define SM_B0 65536
#define SMEM_TOTAL (3 * 65536)

__device__ __nv_bfloat16 g_zn[NROWS * D];   // normalized rows (4 MB, L2-resident)
__device__ float g_part[NROWS * 2];         // per-row exp-sum partial per col-half
__device__ float g_pos[NROWS];              // per-row positive logit

// ---------------------------------------------------------------------------
__device__ __forceinline__ uint32_t smem_u32(const void* p) {
    uint32_t a;
    asm("{ .reg .u64 t; cvta.to.shared.u64 t, %1; cvt.u32.u64 %0, t; }" : "=r"(a) : "l"(p));
    return a;
}
__device__ __forceinline__ void cp16(uint32_t dst, const void* src) {
    asm volatile("cp.async.cg.shared.global [%0], [%1], 16;" :: "r"(dst), "l"(src) : "memory");
}
#define CP_COMMIT() asm volatile("cp.async.commit_group;" ::: "memory")
#define CP_WAIT(n)  asm volatile("cp.async.wait_group %0;" :: "n"(n) : "memory")

__device__ __forceinline__ void ldsm4(uint32_t* r, uint32_t addr) {
    asm volatile("ldmatrix.sync.aligned.m8n8.x4.shared.b16 {%0,%1,%2,%3}, [%4];"
        : "=r"(r[0]), "=r"(r[1]), "=r"(r[2]), "=r"(r[3]) : "r"(addr));
}
__device__ __forceinline__ void mma16816(float* c, const uint32_t* a,
                                         uint32_t b0, uint32_t b1) {
    asm volatile("mma.sync.aligned.m16n8k16.row.col.f32.bf16.bf16.f32 "
        "{%0,%1,%2,%3}, {%4,%5,%6,%7}, {%8,%9}, {%0,%1,%2,%3};"
        : "+f"(c[0]), "+f"(c[1]), "+f"(c[2]), "+f"(c[3])
        : "r"(a[0]), "r"(a[1]), "r"(a[2]), "r"(a[3]), "r"(b0), "r"(b1));
}

// ---------------------------------------------------------------------------
// Kernel 1: L2-normalize rows -> bf16. One warp per row.
// ---------------------------------------------------------------------------
__global__ void __launch_bounds__(256) norm_kernel(const float* __restrict__ z1,
                                                   const float* __restrict__ z2) {
    int wid = threadIdx.x >> 5, lid = threadIdx.x & 31;
    int row = blockIdx.x * 8 + wid;
    const float* src = (row < HALF_N) ? z1 + (size_t)row * D
                                      : z2 + (size_t)(row - HALF_N) * D;
    const float4* s4 = (const float4*)src;
    float4 a = s4[lid], b = s4[lid + 32];
    float ss = a.x*a.x + a.y*a.y + a.z*a.z + a.w*a.w
             + b.x*b.x + b.y*b.y + b.z*b.z + b.w*b.w;
    #pragma unroll
    for (int o = 16; o > 0; o >>= 1) ss += __shfl_xor_sync(0xffffffffu, ss, o);
    float inv = 1.0f / fmaxf(sqrtf(ss), 1e-8f);
    __nv_bfloat162* d2 = (__nv_bfloat162*)(g_zn + (size_t)row * D);
    d2[2*lid]        = __floats2bfloat162_rn(a.x*inv, a.y*inv);
    d2[2*lid + 1]    = __floats2bfloat162_rn(a.z*inv, a.w*inv);
    d2[2*(lid+32)]   = __floats2bfloat162_rn(b.x*inv, b.y*inv);
    d2[2*(lid+32)+1] = __floats2bfloat162_rn(b.z*inv, b.w*inv);
}

// ---------------------------------------------------------------------------
// Kernel 2: mma.sync sim GEMM, warp tile m64 x n64, NT=256 with K-split B.
// Grid 128 = 64 row-blocks x 2 col-halves. 8 warps = 2 row-groups x 4 col-groups.
// Pipeline step t = 2*j + kh: B chunk = 256 col-rows x K-half (64 KB).
// ---------------------------------------------------------------------------
__global__ void __launch_bounds__(THREADS, 1) sim_kernel() {
    extern __shared__ char smem[];
    __shared__ float rowsum[MT];
    uint32_t sb = smem_u32(smem);

    int tid = threadIdx.x, wid = tid >> 5, lane = tid & 31;
    int rb = blockIdx.x >> 1, half = blockIdx.x & 1;
    int rg = wid >> 2;          // row group: rows rg*64 .. +63
    int cg = wid & 3;           // col group: cols cg*64 .. +63

    if (tid < MT) rowsum[tid] = 0.0f;

    const char* gA = (const char*)(g_zn + (size_t)rb * MT * D);
    const char* gB = (const char*)(g_zn + (size_t)half * HALF_N * D);

    // ---- prologue: A (full K, 4096 16B-chunks, swizzled 512B rows) + B steps 0,1
    #pragma unroll
    for (int i = 0; i < 16; i++) {               // 4096 chunks / 256 threads
        uint32_t c = i * 256 + tid;              // chunk: row = c>>5, ch = c&31
        uint32_t r = c >> 5, ch = c & 31;
        cp16(sb + SM_A + r * 512 + ((ch ^ (r & 7)) << 4), gA + (size_t)c * 16);
    }
    {   // B step 0 (j=0, kh=0): 4096 chunks, row = c>>4 (256B rows), ch = c&15
        #pragma unroll
        for (int i = 0; i < 16; i++) {
            uint32_t c = i * 256 + tid, r = c >> 4, ch = c & 15;
            cp16(sb + SM_B0 + r * 256 + ((ch ^ (r & 7)) << 4),
                 gB + (size_t)r * 512 + ch * 16);
        }
    }
    CP_COMMIT();                                 // g0 = A + B(t=0)
    {   // B step 1 (j=0, kh=1)
        #pragma unroll
        for (int i = 0; i < 16; i++) {
            uint32_t c = i * 256 + tid, r = c >> 4, ch = c & 15;
            cp16(sb + SM_B0 + 65536 + r * 256 + ((ch ^ (r & 7)) << 4),
                 gB + (size_t)r * 512 + 256 + ch * 16);
        }
    }
    CP_COMMIT();                                 // g1 = B(t=1)

    // ---- per-lane ldsm row components
    uint32_t lrow = lane & 15;                   // row within 16-row block
    uint32_t lch  = lane >> 4;                   // chunk +0 / +1
    uint32_t aBase[4], aSwz[4], bRow[4], bSwz[4];
    #pragma unroll
    for (int q = 0; q < 4; q++) {
        uint32_t ar = rg * 64 + q * 16 + lrow;
        aBase[q] = sb + SM_A + ar * 512; aSwz[q] = ar & 7;
        uint32_t br = cg * 64 + q * 16 + lrow;
        bRow[q] = br * 256; bSwz[q] = br & 7;
    }

    // ---- epilogue identity
    int rlocBase = rg * 64 + (lane >> 2);        // + q*16 + 8*h
    int giBase   = rb * MT + rlocBase;
    int colBase  = half * HALF_N + cg * 64 + ((lane & 3) << 1);
    int js       = (rb & 31) >> 1;               // the one special j-tile
    bool diagCta = (half == (rb >> 5));

    float acc[4][8][4];
    float rsum[4][2];
    #pragma unroll
    for (int q = 0; q < 4; q++) { rsum[q][0] = 0.f; rsum[q][1] = 0.f; }

    for (int t = 0; t < NSTEP; t++) {
        int j = t >> 1, kh = t & 1;
        if (t == NSTEP - 1) { CP_WAIT(0); } else { CP_WAIT(1); }
        __syncthreads();
        uint32_t bBuf = sb + SM_B0 + (uint32_t)(t & 1) * 65536;

        if (kh == 0) {
            #pragma unroll
            for (int q = 0; q < 4; q++)
                #pragma unroll
                for (int nb = 0; nb < 8; nb++)
                    #pragma unroll
                    for (int e = 0; e < 4; e++) acc[q][nb][e] = 0.f;
        }

        #pragma unroll
        for (int k = 0; k < 8; k++) {
            uint32_t chA = (uint32_t)(kh * 16) + 2 * k + lch;
            uint32_t chB = 2 * k + lch;
            uint32_t a[4][4], b[4][4];
            #pragma unroll
            for (int q = 0; q < 4; q++)
                ldsm4(a[q], aBase[q] + ((chA ^ aSwz[q]) << 4));
            #pragma unroll
            for (int q = 0; q < 4; q++)
                ldsm4(b[q], bBuf + bRow[q] + ((chB ^ bSwz[q]) << 4));
            #pragma unroll
            for (int m = 0; m < 4; m++)
                #pragma unroll
                for (int q = 0; q < 4; q++) {
                    mma16816(acc[m][2*q],   a[m], b[q][0], b[q][2]);
                    mma16816(acc[m][2*q+1], a[m], b[q][1], b[q][3]);
                }
        }

        __syncthreads();                         // all warps done reading bBuf
        if (t + 2 < NSTEP) {                     // prefetch step t+2 into bBuf
            int j2 = (t + 2) >> 1, kh2 = (t + 2) & 1;
            const char* src = gB + (size_t)j2 * NT * 512 + kh2 * 256;
            #pragma unroll
            for (int i = 0; i < 16; i++) {
                uint32_t c = i * 256 + tid, r = c >> 4, ch = c & 15;
                cp16(bBuf + r * 256 + ((ch ^ (r & 7)) << 4),
                     src + (size_t)r * 512 + ch * 16);
            }
            CP_COMMIT();
        }

        // ---- fused epilogue after the second K-half
        if (kh == 1) {
            if (j != js) {
                #pragma unroll
                for (int m = 0; m < 4; m++)
                    #pragma unroll
                    for (int nb = 0; nb < 8; nb++)
                        #pragma unroll
                        for (int e2 = 0; e2 < 4; e2++)
                            rsum[m][e2 >> 1] += __expf(2.f * acc[m][nb][e2]);
            } else {
                #pragma unroll
                for (int m = 0; m < 4; m++) {
                    #pragma unroll
                    for (int e2 = 0; e2 < 4; e2++) {
                        int h = e2 >> 1;
                        int gi = giBase + m * 16 + 8 * h;
                        int gtgt = diagCta ? gi
                                           : ((gi < HALF_N) ? gi + HALF_N : gi - HALF_N);
                        #pragma unroll
                        for (int nb = 0; nb < 8; nb++) {
                            float sim = 2.f * acc[m][nb][e2];
                            int gj = colBase + j * NT + nb * 8 + (e2 & 1);
                            if (diagCta) {
                                if (gj != gtgt) rsum[m][h] += __expf(sim);
                            } else {
                                rsum[m][h] += __expf(sim);
                                if (gj == gtgt) g_pos[gi] = sim;
                            }
                        }
                    }
                }
            }
        }
    }

    // ---- reduce: 4 lanes share a row; 4 col-group warps combine via smem
    #pragma unroll
    for (int q = 0; q < 4; q++)
        #pragma unroll
        for (int h = 0; h < 2; h++) {
            float v = rsum[q][h];
            v += __shfl_xor_sync(0xffffffffu, v, 1);
            v += __shfl_xor_sync(0xffffffffu, v, 2);
            if ((lane & 3) == 0)
                atomicAdd(&rowsum[rlocBase + q * 16 + 8 * h], v);
        }
    __syncthreads();
    if (tid < MT)
        g_part[(size_t)(rb * MT + tid) * 2 + half] = rowsum[tid];
}

// ---------------------------------------------------------------------------
// Kernel 3: combine partials -> mean loss.
// ---------------------------------------------------------------------------
__global__ void reduce_kernel(float* __restrict__ out) {
    __shared__ float red[256];
    int t = threadIdx.x;
    float s = 0.0f;
    for (int i = t; i < NROWS; i += 256)
        s += logf(g_part[2*i] + g_part[2*i + 1]) - g_pos[i];
    red[t] = s;
    __syncthreads();
    #pragma unroll
    for (int k = 128; k > 0; k >>= 1) {
        if (t < k) red[t] += red[t + k];
        __syncthreads();
    }
    if (t == 0) out[0] = red[0] / (float)NROWS;
}

// ---------------------------------------------------------------------------
extern "C" void kernel_launch(void* const* d_in, const int* in_sizes, int n_in,
                              void* d_out, int out_size) {
    const float* z1 = (const float*)d_in[0];
    const float* z2 = (const float*)d_in[1];
    float* out = (float*)d_out;

    cudaFuncSetAttribute(sim_kernel,
                         cudaFuncAttributeMaxDynamicSharedMemorySize, SMEM_TOTAL);

    norm_kernel<<<NROWS / 8, 256>>>(z1, z2);
    sim_kernel<<<128, THREADS, SMEM_TOTAL>>>();
    reduce_kernel<<<1, 256>>>(out);
}